// round 3
// baseline (speedup 1.0000x reference)
#include <cuda_runtime.h>
#include <math.h>

// Problem constants
#define NB      8192      // batch
#define ND      32        // dims
#define NK      64        // mixture components
#define NSTEP   255       // Euler-Maruyama steps (N_ITER - 1)
#define TPB     256       // threads per block
#define GSIZE   4         // threads cooperating per sample (K split)
#define KPER    (NK / GSIZE)   // 16 components per thread
#define STRIDE  36        // smem row stride in floats (144B, 16B aligned)
#define NBLK    148       // one block per SM
// 52 blocks get 56 samples, 96 blocks get 55:  52*56 + 96*55 = 8192

typedef unsigned long long u64;

__device__ __forceinline__ u64 pk2(float lo, float hi) {
    u64 r; asm("mov.b64 %0, {%1, %2};" : "=l"(r) : "f"(lo), "f"(hi)); return r;
}
__device__ __forceinline__ void upk2(u64 v, float& lo, float& hi) {
    asm("mov.b64 {%0, %1}, %2;" : "=f"(lo), "=f"(hi) : "l"(v));
}
__device__ __forceinline__ u64 add2(u64 a, u64 b) {
    u64 d; asm("add.rn.f32x2 %0, %1, %2;" : "=l"(d) : "l"(a), "l"(b)); return d;
}
__device__ __forceinline__ u64 mul2(u64 a, u64 b) {
    u64 d; asm("mul.rn.f32x2 %0, %1, %2;" : "=l"(d) : "l"(a), "l"(b)); return d;
}
__device__ __forceinline__ u64 fma2_(u64 a, u64 b, u64 c) {
    u64 d; asm("fma.rn.f32x2 %0, %1, %2, %3;" : "=l"(d) : "l"(a), "l"(b), "l"(c)); return d;
}

__global__ __launch_bounds__(TPB, 1)
void sbm_kernel(const float* __restrict__ x_init,
                const float* __restrict__ centers,
                const float* __restrict__ stds,
                const float* __restrict__ weights,
                const float* __restrict__ noise,
                float* __restrict__ out)
{
    __shared__ float sm_nm[NK * STRIDE];   // NEGATED diffused means
    __shared__ float sm_iv[NK * STRIDE];   // inverse diffused variances
    __shared__ float sm_c [NK];            // per-component log constant

    const int tid   = threadIdx.x;
    const int kpart = tid & (GSIZE - 1);
    const int g     = tid >> 2;                        // sample group within block

    const int b     = blockIdx.x;
    const int cnt   = 55 + (b < 52 ? 1 : 0);
    const int base  = 55 * b + min(b, 52);
    const bool writer = (g < cnt) && (kpart == 0);     // only guard the store
    // ALL threads run the compute path (warp-collective shfl safety);
    // overflow groups redo the last sample of the block, result discarded.
    const int sample = base + min(g, cnt - 1);

    // table-build assignment: thread -> (component tk, dim octet td0)
    const int tk  = tid >> 2;            // 0..63
    const int td0 = (tid & 3) * 8;       // 0,8,16,24

    u64 x2[ND/2];
    {
        const ulonglong2* xp = reinterpret_cast<const ulonglong2*>(x_init + (size_t)sample * ND);
        #pragma unroll
        for (int j = 0; j < 8; j++) {
            ulonglong2 v = xp[j];
            x2[2*j]   = v.x;
            x2[2*j+1] = v.y;
        }
    }

    const float T_MAX = 1.0f;
    const float T_MIN = 1e-4f;
    const float H   = (T_MAX - T_MIN) / 255.0f;   // |dt| per step
    const float SQH = sqrtf(H);

    for (int i = 0; i < NSTEP; i++) {
        // schedule scalars
        float t  = T_MAX - (float)i * H;
        float bt = 0.1f + 19.9f * t;                 // beta(t)
        float Bt = 0.1f * t + 9.95f * t * t;         // Beta(t)
        float eB = expf(-Bt);
        float om = 1.0f - eB;
        float sq = sqrtf(eB);
        float hb = H * bt;                           // -dt * beta (positive)
        float sn = sqrtf(bt) * SQH;

        __syncthreads();   // previous step's table readers are done

        // ---- build per-step mixture table in smem (all 256 threads) ----
        {
            float lsum = 0.0f;
            #pragma unroll
            for (int j = 0; j < 8; j++) {
                int d     = td0 + j;
                float c   = centers[tk * ND + d];
                float sd  = stds   [tk * ND + d];
                float v   = eB * sd * sd + om;       // diffused variance
                sm_nm[tk * STRIDE + d] = -(sq * c);  // negated diffused mean
                sm_iv[tk * STRIDE + d] = 1.0f / v;
                lsum += __logf(6.2831853071795864f * v);
            }
            lsum += __shfl_xor_sync(0xffffffffu, lsum, 1);
            lsum += __shfl_xor_sync(0xffffffffu, lsum, 2);
            if ((tid & 3) == 0) {
                // reference: -(0.5*D) * sum(log(2*pi*v)) + log(w)   with D = 32
                sm_c[tk] = fmaf(-16.0f, lsum, __logf(weights[tk]));
            }
        }
        __syncthreads();

        // ---- online softmax over this thread's 16 components (packed f32x2) ----
        float M = -INFINITY;
        float S = 0.0f;
        u64 acc2[ND/2];
        u64 dv2 [ND/2];
        #pragma unroll
        for (int p = 0; p < ND/2; p++) acc2[p] = 0ull;   // (0.f, 0.f)

        for (int kk = 0; kk < KPER; kk++) {
            int k = kk * GSIZE + kpart;   // consecutive k across the 4-thread group
            const ulonglong2* nmp = reinterpret_cast<const ulonglong2*>(sm_nm + k * STRIDE);
            const ulonglong2* ivp = reinterpret_cast<const ulonglong2*>(sm_iv + k * STRIDE);

            u64 sA = 0ull, sB = 0ull;
            #pragma unroll
            for (int j = 0; j < 8; j++) {
                ulonglong2 nm = nmp[j];
                ulonglong2 iv = ivp[j];
                u64 a0 = add2(x2[2*j],   nm.x);   // x - m
                u64 a1 = add2(x2[2*j+1], nm.y);
                u64 b0 = mul2(a0, iv.x);          // (x-m)/v
                u64 b1 = mul2(a1, iv.y);
                sA = fma2_(b0, a0, sA);           // (x-m)^2/v
                sB = fma2_(b1, a1, sB);
                dv2[2*j]   = b0;
                dv2[2*j+1] = b1;
            }
            float sa0, sa1, sb0, sb1;
            upk2(sA, sa0, sa1);
            upk2(sB, sb0, sb1);
            float s = (sa0 + sb0) + (sa1 + sb1);
            float logc = fmaf(-0.5f, s, sm_c[k]);

            if (logc > M) {
                float r = __expf(M - logc);       // exp(-inf)=0 handles first k
                u64 r2 = pk2(r, r);
                S = fmaf(S, r, 1.0f);
                #pragma unroll
                for (int p = 0; p < ND/2; p++) acc2[p] = fma2_(acc2[p], r2, dv2[p]);
                M = logc;
            } else {
                float w = __expf(logc - M);
                u64 w2 = pk2(w, w);
                S += w;
                #pragma unroll
                for (int p = 0; p < ND/2; p++) acc2[p] = fma2_(w2, dv2[p], acc2[p]);
            }
        }

        // ---- merge 4 partial softmax states (xor 1, xor 2) ----
        #pragma unroll
        for (int r = 1; r <= 2; r <<= 1) {
            float Mo = __shfl_xor_sync(0xffffffffu, M, r);
            float So = __shfl_xor_sync(0xffffffffu, S, r);
            float Mn = fmaxf(M, Mo);
            float es = __expf(M  - Mn);
            float eo = __expf(Mo - Mn);
            S = S * es + So * eo;
            u64 es2 = pk2(es, es);
            u64 eo2 = pk2(eo, eo);
            #pragma unroll
            for (int p = 0; p < ND/2; p++) {
                u64 ao = __shfl_xor_sync(0xffffffffu, acc2[p], r);
                acc2[p] = fma2_(acc2[p], es2, mul2(ao, eo2));
            }
            M = Mn;
        }

        // ---- Euler-Maruyama update (packed) ----
        float invS = 1.0f / S;
        u64 minv2 = pk2(-invS, -invS);
        u64 half2 = pk2(0.5f, 0.5f);
        u64 hb2   = pk2(hb, hb);
        u64 sn2   = pk2(sn, sn);
        const ulonglong2* np = reinterpret_cast<const ulonglong2*>(
            noise + ((size_t)i * NB + (size_t)sample) * ND);
        #pragma unroll
        for (int j = 0; j < 8; j++) {
            ulonglong2 z = np[j];
            // c = 0.5*x - invS*acc  (drift/beta, sign folded);  x += hb*c + sn*z
            u64 c0 = fma2_(minv2, acc2[2*j],   mul2(half2, x2[2*j]));
            u64 c1 = fma2_(minv2, acc2[2*j+1], mul2(half2, x2[2*j+1]));
            x2[2*j]   = fma2_(sn2, z.x, fma2_(hb2, c0, x2[2*j]));
            x2[2*j+1] = fma2_(sn2, z.y, fma2_(hb2, c1, x2[2*j+1]));
        }
    }

    // ---- write final x (one thread per sample) ----
    if (writer) {
        ulonglong2* op = reinterpret_cast<ulonglong2*>(out + (size_t)sample * ND);
        #pragma unroll
        for (int j = 0; j < 8; j++) {
            ulonglong2 v;
            v.x = x2[2*j];
            v.y = x2[2*j+1];
            op[j] = v;
        }
    }
}

extern "C" void kernel_launch(void* const* d_in, const int* in_sizes, int n_in,
                              void* d_out, int out_size)
{
    const float* x_init  = (const float*)d_in[0];
    const float* centers = (const float*)d_in[1];
    const float* stds    = (const float*)d_in[2];
    const float* weights = (const float*)d_in[3];
    const float* noise   = (const float*)d_in[4];
    float* out = (float*)d_out;

    sbm_kernel<<<NBLK, TPB>>>(x_init, centers, stds, weights, noise, out);
}

// round 4
// speedup vs baseline: 1.0769x; 1.0769x over previous
#include <cuda_runtime.h>
#include <math.h>

// Problem constants
#define NB      8192      // batch
#define ND      32        // dims
#define NK      64        // mixture components
#define NSTEP   255       // Euler-Maruyama steps (N_ITER - 1)
#define TPB     224       // 7 warps: 28 groups of 8 threads
#define GSIZE   8         // threads per group (K split); each group does 2 samples
#define KPER    (NK / GSIZE)   // 8 components per thread
#define STRIDE  36        // smem row stride in floats (144B, 16B aligned, conflict-free)
#define NBLK    148       // one block per SM
// 52 blocks x 56 samples + 96 blocks x 55 samples = 8192

__global__ __launch_bounds__(TPB, 1)
void sbm_kernel(const float* __restrict__ x_init,
                const float* __restrict__ centers,
                const float* __restrict__ stds,
                const float* __restrict__ weights,
                const float* __restrict__ noise,
                float* __restrict__ out)
{
    __shared__ float sm_nm[NK * STRIDE];   // NEGATED diffused means
    __shared__ float sm_iv[NK * STRIDE];   // inverse diffused variances
    __shared__ float sm_c [NK];            // per-component log constant

    const int tid   = threadIdx.x;
    const int kpart = tid & (GSIZE - 1);   // 0..7
    const int g     = tid >> 3;            // group 0..27

    const int b    = blockIdx.x;
    const int cnt  = (b < 52) ? 56 : 55;
    const int base = 55 * b + min(b, 52);

    // two samples per thread; slot 2g always valid (2*27=54 < 55), slot 2g+1 may clamp
    const int  s0 = base + 2 * g;
    const bool v1 = (2 * g + 1) < cnt;
    const int  s1 = base + min(2 * g + 1, cnt - 1);

    float x0[ND], x1[ND];
    {
        const float4* p0 = reinterpret_cast<const float4*>(x_init + (size_t)s0 * ND);
        const float4* p1 = reinterpret_cast<const float4*>(x_init + (size_t)s1 * ND);
        #pragma unroll
        for (int j = 0; j < 8; j++) {
            float4 a = p0[j], c = p1[j];
            x0[4*j+0]=a.x; x0[4*j+1]=a.y; x0[4*j+2]=a.z; x0[4*j+3]=a.w;
            x1[4*j+0]=c.x; x1[4*j+1]=c.y; x1[4*j+2]=c.z; x1[4*j+3]=c.w;
        }
    }

    const float T_MAX = 1.0f;
    const float T_MIN = 1e-4f;
    const float H   = (T_MAX - T_MIN) / 255.0f;
    const float SQH = sqrtf(H);

    for (int i = 0; i < NSTEP; i++) {
        float t  = T_MAX - (float)i * H;
        float bt = 0.1f + 19.9f * t;                 // beta(t)
        float Bt = 0.1f * t + 9.95f * t * t;         // Beta(t)
        float eB = expf(-Bt);
        float om = 1.0f - eB;
        float sq = sqrtf(eB);
        float hb = H * bt;                           // -dt * beta (positive)
        float sn = sqrtf(bt) * SQH;

        __syncthreads();   // previous step's table readers are done

        // ---- build per-step mixture table (threads 0..127 = warps 0-3) ----
        if (tid < 128) {
            int k = tid >> 1;
            int h = (tid & 1) * 16;                  // dim half: 0 or 16
            float lsum = 0.0f;
            #pragma unroll
            for (int jj = 0; jj < 4; jj++) {
                int d = h + jj * 4;
                float4 c4 = *reinterpret_cast<const float4*>(centers + k * ND + d);
                float4 s4 = *reinterpret_cast<const float4*>(stds    + k * ND + d);
                float v0 = eB * s4.x * s4.x + om;
                float v1v= eB * s4.y * s4.y + om;
                float v2 = eB * s4.z * s4.z + om;
                float v3 = eB * s4.w * s4.w + om;
                float4 nm4 = make_float4(-(sq*c4.x), -(sq*c4.y), -(sq*c4.z), -(sq*c4.w));
                float4 iv4 = make_float4(1.0f/v0, 1.0f/v1v, 1.0f/v2, 1.0f/v3);
                *reinterpret_cast<float4*>(sm_nm + k * STRIDE + d) = nm4;
                *reinterpret_cast<float4*>(sm_iv + k * STRIDE + d) = iv4;
                const float TWO_PI = 6.2831853071795864f;
                lsum += __logf(TWO_PI*v0) + __logf(TWO_PI*v1v)
                      + __logf(TWO_PI*v2) + __logf(TWO_PI*v3);
            }
            lsum += __shfl_xor_sync(0xffffffffu, lsum, 1);
            if ((tid & 1) == 0) {
                // reference: -(0.5*D) * sum(log(2*pi*v)) + log(w),  D = 32
                sm_c[k] = fmaf(-16.0f, lsum, __logf(weights[k]));
            }
        }
        __syncthreads();

        // ---- online softmax over this thread's 8 components, 2 samples ----
        float M0 = -INFINITY, S0 = 0.0f;
        float M1 = -INFINITY, S1 = 0.0f;
        float acc0[ND], acc1[ND];
        float dv0 [ND], dv1 [ND];
        #pragma unroll
        for (int d = 0; d < ND; d++) { acc0[d] = 0.0f; acc1[d] = 0.0f; }

        #pragma unroll 1
        for (int kk = 0; kk < KPER; kk++) {
            int k = kk * GSIZE + kpart;   // lanes 0..7 of a group take consecutive k
            const float4* nmp = reinterpret_cast<const float4*>(sm_nm + k * STRIDE);
            const float4* ivp = reinterpret_cast<const float4*>(sm_iv + k * STRIDE);

            float sa0 = 0.f, sb0 = 0.f, sa1 = 0.f, sb1 = 0.f;
            #pragma unroll
            for (int j = 0; j < 8; j++) {
                float4 m  = nmp[j];
                float4 iv = ivp[j];
                int d = 4 * j;
                // sample 0
                {
                    float a0 = x0[d+0] + m.x;
                    float a1 = x0[d+1] + m.y;
                    float a2 = x0[d+2] + m.z;
                    float a3 = x0[d+3] + m.w;
                    float b0 = a0 * iv.x;
                    float b1 = a1 * iv.y;
                    float b2 = a2 * iv.z;
                    float b3 = a3 * iv.w;
                    sa0 = fmaf(b0, a0, sa0);
                    sb0 = fmaf(b1, a1, sb0);
                    sa0 = fmaf(b2, a2, sa0);
                    sb0 = fmaf(b3, a3, sb0);
                    dv0[d+0] = b0; dv0[d+1] = b1; dv0[d+2] = b2; dv0[d+3] = b3;
                }
                // sample 1
                {
                    float a0 = x1[d+0] + m.x;
                    float a1 = x1[d+1] + m.y;
                    float a2 = x1[d+2] + m.z;
                    float a3 = x1[d+3] + m.w;
                    float b0 = a0 * iv.x;
                    float b1 = a1 * iv.y;
                    float b2 = a2 * iv.z;
                    float b3 = a3 * iv.w;
                    sa1 = fmaf(b0, a0, sa1);
                    sb1 = fmaf(b1, a1, sb1);
                    sa1 = fmaf(b2, a2, sa1);
                    sb1 = fmaf(b3, a3, sb1);
                    dv1[d+0] = b0; dv1[d+1] = b1; dv1[d+2] = b2; dv1[d+3] = b3;
                }
            }
            float cK = sm_c[k];
            float logc0 = fmaf(-0.5f, sa0 + sb0, cK);
            float logc1 = fmaf(-0.5f, sa1 + sb1, cK);

            // sample 0 online-softmax update
            if (logc0 > M0) {
                float r = __expf(M0 - logc0);        // exp(-inf)=0 handles first k
                S0 = fmaf(S0, r, 1.0f);
                #pragma unroll
                for (int d = 0; d < ND; d++) acc0[d] = fmaf(acc0[d], r, dv0[d]);
                M0 = logc0;
            } else {
                float w = __expf(logc0 - M0);
                S0 += w;
                #pragma unroll
                for (int d = 0; d < ND; d++) acc0[d] = fmaf(w, dv0[d], acc0[d]);
            }
            // sample 1 online-softmax update
            if (logc1 > M1) {
                float r = __expf(M1 - logc1);
                S1 = fmaf(S1, r, 1.0f);
                #pragma unroll
                for (int d = 0; d < ND; d++) acc1[d] = fmaf(acc1[d], r, dv1[d]);
                M1 = logc1;
            } else {
                float w = __expf(logc1 - M1);
                S1 += w;
                #pragma unroll
                for (int d = 0; d < ND; d++) acc1[d] = fmaf(w, dv1[d], acc1[d]);
            }
        }

        // ---- merge 8 partial softmax states (xor 1, 2, 4) ----
        #pragma unroll
        for (int r = 1; r <= 4; r <<= 1) {
            // sample 0
            {
                float Mo = __shfl_xor_sync(0xffffffffu, M0, r);
                float So = __shfl_xor_sync(0xffffffffu, S0, r);
                float Mn = fmaxf(M0, Mo);
                float es = __expf(M0 - Mn);
                float eo = __expf(Mo - Mn);
                S0 = S0 * es + So * eo;
                #pragma unroll
                for (int d = 0; d < ND; d++) {
                    float ao = __shfl_xor_sync(0xffffffffu, acc0[d], r);
                    acc0[d] = acc0[d] * es + ao * eo;
                }
                M0 = Mn;
            }
            // sample 1
            {
                float Mo = __shfl_xor_sync(0xffffffffu, M1, r);
                float So = __shfl_xor_sync(0xffffffffu, S1, r);
                float Mn = fmaxf(M1, Mo);
                float es = __expf(M1 - Mn);
                float eo = __expf(Mo - Mn);
                S1 = S1 * es + So * eo;
                #pragma unroll
                for (int d = 0; d < ND; d++) {
                    float ao = __shfl_xor_sync(0xffffffffu, acc1[d], r);
                    acc1[d] = acc1[d] * es + ao * eo;
                }
                M1 = Mn;
            }
        }

        // ---- Euler-Maruyama update, both samples ----
        float i0 = 1.0f / S0;
        float i1 = 1.0f / S1;
        const float4* n0 = reinterpret_cast<const float4*>(
            noise + ((size_t)i * NB + (size_t)s0) * ND);
        const float4* n1 = reinterpret_cast<const float4*>(
            noise + ((size_t)i * NB + (size_t)s1) * ND);
        #pragma unroll
        for (int j = 0; j < 8; j++) {
            float4 z0 = n0[j];
            float4 z1 = n1[j];
            int d = 4 * j;
            // c = 0.5*x - invS*acc ;  x += hb*c + sn*z
            float c0 = fmaf(-i0, acc0[d+0], 0.5f * x0[d+0]);
            float c1 = fmaf(-i0, acc0[d+1], 0.5f * x0[d+1]);
            float c2 = fmaf(-i0, acc0[d+2], 0.5f * x0[d+2]);
            float c3 = fmaf(-i0, acc0[d+3], 0.5f * x0[d+3]);
            x0[d+0] = fmaf(sn, z0.x, fmaf(hb, c0, x0[d+0]));
            x0[d+1] = fmaf(sn, z0.y, fmaf(hb, c1, x0[d+1]));
            x0[d+2] = fmaf(sn, z0.z, fmaf(hb, c2, x0[d+2]));
            x0[d+3] = fmaf(sn, z0.w, fmaf(hb, c3, x0[d+3]));

            float e0 = fmaf(-i1, acc1[d+0], 0.5f * x1[d+0]);
            float e1 = fmaf(-i1, acc1[d+1], 0.5f * x1[d+1]);
            float e2 = fmaf(-i1, acc1[d+2], 0.5f * x1[d+2]);
            float e3 = fmaf(-i1, acc1[d+3], 0.5f * x1[d+3]);
            x1[d+0] = fmaf(sn, z1.x, fmaf(hb, e0, x1[d+0]));
            x1[d+1] = fmaf(sn, z1.y, fmaf(hb, e1, x1[d+1]));
            x1[d+2] = fmaf(sn, z1.z, fmaf(hb, e2, x1[d+2]));
            x1[d+3] = fmaf(sn, z1.w, fmaf(hb, e3, x1[d+3]));
        }
    }

    // ---- write final x (lane 0 of each group writes its sample pair) ----
    if (kpart == 0) {
        float4* o0 = reinterpret_cast<float4*>(out + (size_t)s0 * ND);
        #pragma unroll
        for (int j = 0; j < 8; j++)
            o0[j] = make_float4(x0[4*j+0], x0[4*j+1], x0[4*j+2], x0[4*j+3]);
        if (v1) {
            float4* o1 = reinterpret_cast<float4*>(out + (size_t)s1 * ND);
            #pragma unroll
            for (int j = 0; j < 8; j++)
                o1[j] = make_float4(x1[4*j+0], x1[4*j+1], x1[4*j+2], x1[4*j+3]);
        }
    }
}

extern "C" void kernel_launch(void* const* d_in, const int* in_sizes, int n_in,
                              void* d_out, int out_size)
{
    const float* x_init  = (const float*)d_in[0];
    const float* centers = (const float*)d_in[1];
    const float* stds    = (const float*)d_in[2];
    const float* weights = (const float*)d_in[3];
    const float* noise   = (const float*)d_in[4];
    float* out = (float*)d_out;

    sbm_kernel<<<NBLK, TPB>>>(x_init, centers, stds, weights, noise, out);
}

// round 5
// speedup vs baseline: 1.0840x; 1.0065x over previous
#include <cuda_runtime.h>
#include <math.h>

// Problem constants
#define NB      8192      // batch
#define ND      32        // dims
#define NK      64        // mixture components
#define NSTEP   255       // Euler-Maruyama steps (N_ITER - 1)
#define TPB     224       // 7 warps: 28 groups of 8 threads
#define GSIZE   8         // threads per group (K split); each group does 2 samples
#define KPER    (NK / GSIZE)   // 8 components per thread
#define STRIDE  36        // smem row stride in floats (144B, 16B aligned, conflict-free)
#define NBLK    148       // one block per SM
// 52 blocks x 56 samples + 96 blocks x 55 samples = 8192

__global__ __launch_bounds__(TPB, 1)
void sbm_kernel(const float* __restrict__ x_init,
                const float* __restrict__ centers,
                const float* __restrict__ stds,
                const float* __restrict__ weights,
                const float* __restrict__ noise,
                float* __restrict__ out)
{
    __shared__ float sm_nm[NK * STRIDE];   // NEGATED diffused means
    __shared__ float sm_iv[NK * STRIDE];   // inverse diffused variances
    __shared__ float sm_c [NK];            // per-component log constant

    const int tid   = threadIdx.x;
    const int kpart = tid & (GSIZE - 1);   // 0..7
    const int g     = tid >> 3;            // group 0..27

    const int b    = blockIdx.x;
    const int cnt  = (b < 52) ? 56 : 55;
    const int base = 55 * b + min(b, 52);

    // two samples per thread; slot 2g always valid (2*27=54 < 55), slot 2g+1 may clamp
    const int  s0 = base + 2 * g;
    const bool v1 = (2 * g + 1) < cnt;
    const int  s1 = base + min(2 * g + 1, cnt - 1);

    float x0[ND], x1[ND];
    {
        const float4* p0 = reinterpret_cast<const float4*>(x_init + (size_t)s0 * ND);
        const float4* p1 = reinterpret_cast<const float4*>(x_init + (size_t)s1 * ND);
        #pragma unroll
        for (int j = 0; j < 8; j++) {
            float4 a = p0[j], c = p1[j];
            x0[4*j+0]=a.x; x0[4*j+1]=a.y; x0[4*j+2]=a.z; x0[4*j+3]=a.w;
            x1[4*j+0]=c.x; x1[4*j+1]=c.y; x1[4*j+2]=c.z; x1[4*j+3]=c.w;
        }
    }

    const float T_MAX = 1.0f;
    const float T_MIN = 1e-4f;
    const float H   = (T_MAX - T_MIN) / 255.0f;
    const float SQH = sqrtf(H);

    for (int i = 0; i < NSTEP; i++) {
        float t  = T_MAX - (float)i * H;
        float bt = 0.1f + 19.9f * t;                 // beta(t)
        float Bt = 0.1f * t + 9.95f * t * t;         // Beta(t)
        float eB = expf(-Bt);
        float om = 1.0f - eB;
        float sq = sqrtf(eB);
        float hb = H * bt;                           // -dt * beta (positive)
        float sn = sqrtf(bt) * SQH;

        __syncthreads();   // previous step's table readers are done

        // ---- build per-step mixture table (threads 0..127 = warps 0-3) ----
        if (tid < 128) {
            int k = tid >> 1;
            int h = (tid & 1) * 16;                  // dim half: 0 or 16
            float lsum = 0.0f;
            #pragma unroll
            for (int jj = 0; jj < 4; jj++) {
                int d = h + jj * 4;
                float4 c4 = *reinterpret_cast<const float4*>(centers + k * ND + d);
                float4 s4 = *reinterpret_cast<const float4*>(stds    + k * ND + d);
                float v0 = eB * s4.x * s4.x + om;
                float v1v= eB * s4.y * s4.y + om;
                float v2 = eB * s4.z * s4.z + om;
                float v3 = eB * s4.w * s4.w + om;
                float4 nm4 = make_float4(-(sq*c4.x), -(sq*c4.y), -(sq*c4.z), -(sq*c4.w));
                float4 iv4 = make_float4(1.0f/v0, 1.0f/v1v, 1.0f/v2, 1.0f/v3);
                *reinterpret_cast<float4*>(sm_nm + k * STRIDE + d) = nm4;
                *reinterpret_cast<float4*>(sm_iv + k * STRIDE + d) = iv4;
                const float TWO_PI = 6.2831853071795864f;
                lsum += __logf(TWO_PI*v0) + __logf(TWO_PI*v1v)
                      + __logf(TWO_PI*v2) + __logf(TWO_PI*v3);
            }
            lsum += __shfl_xor_sync(0xffffffffu, lsum, 1);
            if ((tid & 1) == 0) {
                // reference: -(0.5*D) * sum(log(2*pi*v)) + log(w),  D = 32
                sm_c[k] = fmaf(-16.0f, lsum, __logf(weights[k]));
            }
        }
        __syncthreads();

        // ---- online softmax over this thread's 8 components, 2 samples ----
        float M0 = -INFINITY, S0 = 0.0f;
        float M1 = -INFINITY, S1 = 0.0f;
        float acc0[ND], acc1[ND];
        float dv0 [ND], dv1 [ND];
        #pragma unroll
        for (int d = 0; d < ND; d++) { acc0[d] = 0.0f; acc1[d] = 0.0f; }

        #pragma unroll 1
        for (int kk = 0; kk < KPER; kk++) {
            int k = kk * GSIZE + kpart;   // lanes 0..7 of a group take consecutive k
            const float4* nmp = reinterpret_cast<const float4*>(sm_nm + k * STRIDE);
            const float4* ivp = reinterpret_cast<const float4*>(sm_iv + k * STRIDE);

            float sa0 = 0.f, sb0 = 0.f, sa1 = 0.f, sb1 = 0.f;
            #pragma unroll
            for (int j = 0; j < 8; j++) {
                float4 m  = nmp[j];
                float4 iv = ivp[j];
                int d = 4 * j;
                // sample 0
                {
                    float a0 = x0[d+0] + m.x;
                    float a1 = x0[d+1] + m.y;
                    float a2 = x0[d+2] + m.z;
                    float a3 = x0[d+3] + m.w;
                    float b0 = a0 * iv.x;
                    float b1 = a1 * iv.y;
                    float b2 = a2 * iv.z;
                    float b3 = a3 * iv.w;
                    sa0 = fmaf(b0, a0, sa0);
                    sb0 = fmaf(b1, a1, sb0);
                    sa0 = fmaf(b2, a2, sa0);
                    sb0 = fmaf(b3, a3, sb0);
                    dv0[d+0] = b0; dv0[d+1] = b1; dv0[d+2] = b2; dv0[d+3] = b3;
                }
                // sample 1
                {
                    float a0 = x1[d+0] + m.x;
                    float a1 = x1[d+1] + m.y;
                    float a2 = x1[d+2] + m.z;
                    float a3 = x1[d+3] + m.w;
                    float b0 = a0 * iv.x;
                    float b1 = a1 * iv.y;
                    float b2 = a2 * iv.z;
                    float b3 = a3 * iv.w;
                    sa1 = fmaf(b0, a0, sa1);
                    sb1 = fmaf(b1, a1, sb1);
                    sa1 = fmaf(b2, a2, sa1);
                    sb1 = fmaf(b3, a3, sb1);
                    dv1[d+0] = b0; dv1[d+1] = b1; dv1[d+2] = b2; dv1[d+3] = b3;
                }
            }
            float cK = sm_c[k];
            float logc0 = fmaf(-0.5f, sa0 + sb0, cK);
            float logc1 = fmaf(-0.5f, sa1 + sb1, cK);

            // sample 0 online-softmax update
            if (logc0 > M0) {
                float r = __expf(M0 - logc0);        // exp(-inf)=0 handles first k
                S0 = fmaf(S0, r, 1.0f);
                #pragma unroll
                for (int d = 0; d < ND; d++) acc0[d] = fmaf(acc0[d], r, dv0[d]);
                M0 = logc0;
            } else {
                float w = __expf(logc0 - M0);
                S0 += w;
                #pragma unroll
                for (int d = 0; d < ND; d++) acc0[d] = fmaf(w, dv0[d], acc0[d]);
            }
            // sample 1 online-softmax update
            if (logc1 > M1) {
                float r = __expf(M1 - logc1);
                S1 = fmaf(S1, r, 1.0f);
                #pragma unroll
                for (int d = 0; d < ND; d++) acc1[d] = fmaf(acc1[d], r, dv1[d]);
                M1 = logc1;
            } else {
                float w = __expf(logc1 - M1);
                S1 += w;
                #pragma unroll
                for (int d = 0; d < ND; d++) acc1[d] = fmaf(w, dv1[d], acc1[d]);
            }
        }

        // ---- merge 8 partial softmax states (xor 1, 2, 4) ----
        #pragma unroll
        for (int r = 1; r <= 4; r <<= 1) {
            // sample 0
            {
                float Mo = __shfl_xor_sync(0xffffffffu, M0, r);
                float So = __shfl_xor_sync(0xffffffffu, S0, r);
                float Mn = fmaxf(M0, Mo);
                float es = __expf(M0 - Mn);
                float eo = __expf(Mo - Mn);
                S0 = S0 * es + So * eo;
                #pragma unroll
                for (int d = 0; d < ND; d++) {
                    float ao = __shfl_xor_sync(0xffffffffu, acc0[d], r);
                    acc0[d] = acc0[d] * es + ao * eo;
                }
                M0 = Mn;
            }
            // sample 1
            {
                float Mo = __shfl_xor_sync(0xffffffffu, M1, r);
                float So = __shfl_xor_sync(0xffffffffu, S1, r);
                float Mn = fmaxf(M1, Mo);
                float es = __expf(M1 - Mn);
                float eo = __expf(Mo - Mn);
                S1 = S1 * es + So * eo;
                #pragma unroll
                for (int d = 0; d < ND; d++) {
                    float ao = __shfl_xor_sync(0xffffffffu, acc1[d], r);
                    acc1[d] = acc1[d] * es + ao * eo;
                }
                M1 = Mn;
            }
        }

        // ---- Euler-Maruyama update, both samples ----
        float i0 = 1.0f / S0;
        float i1 = 1.0f / S1;
        const float4* n0 = reinterpret_cast<const float4*>(
            noise + ((size_t)i * NB + (size_t)s0) * ND);
        const float4* n1 = reinterpret_cast<const float4*>(
            noise + ((size_t)i * NB + (size_t)s1) * ND);
        #pragma unroll
        for (int j = 0; j < 8; j++) {
            float4 z0 = n0[j];
            float4 z1 = n1[j];
            int d = 4 * j;
            // c = 0.5*x - invS*acc ;  x += hb*c + sn*z
            float c0 = fmaf(-i0, acc0[d+0], 0.5f * x0[d+0]);
            float c1 = fmaf(-i0, acc0[d+1], 0.5f * x0[d+1]);
            float c2 = fmaf(-i0, acc0[d+2], 0.5f * x0[d+2]);
            float c3 = fmaf(-i0, acc0[d+3], 0.5f * x0[d+3]);
            x0[d+0] = fmaf(sn, z0.x, fmaf(hb, c0, x0[d+0]));
            x0[d+1] = fmaf(sn, z0.y, fmaf(hb, c1, x0[d+1]));
            x0[d+2] = fmaf(sn, z0.z, fmaf(hb, c2, x0[d+2]));
            x0[d+3] = fmaf(sn, z0.w, fmaf(hb, c3, x0[d+3]));

            float e0 = fmaf(-i1, acc1[d+0], 0.5f * x1[d+0]);
            float e1 = fmaf(-i1, acc1[d+1], 0.5f * x1[d+1]);
            float e2 = fmaf(-i1, acc1[d+2], 0.5f * x1[d+2]);
            float e3 = fmaf(-i1, acc1[d+3], 0.5f * x1[d+3]);
            x1[d+0] = fmaf(sn, z1.x, fmaf(hb, e0, x1[d+0]));
            x1[d+1] = fmaf(sn, z1.y, fmaf(hb, e1, x1[d+1]));
            x1[d+2] = fmaf(sn, z1.z, fmaf(hb, e2, x1[d+2]));
            x1[d+3] = fmaf(sn, z1.w, fmaf(hb, e3, x1[d+3]));
        }
    }

    // ---- write final x (lane 0 of each group writes its sample pair) ----
    if (kpart == 0) {
        float4* o0 = reinterpret_cast<float4*>(out + (size_t)s0 * ND);
        #pragma unroll
        for (int j = 0; j < 8; j++)
            o0[j] = make_float4(x0[4*j+0], x0[4*j+1], x0[4*j+2], x0[4*j+3]);
        if (v1) {
            float4* o1 = reinterpret_cast<float4*>(out + (size_t)s1 * ND);
            #pragma unroll
            for (int j = 0; j < 8; j++)
                o1[j] = make_float4(x1[4*j+0], x1[4*j+1], x1[4*j+2], x1[4*j+3]);
        }
    }
}

extern "C" void kernel_launch(void* const* d_in, const int* in_sizes, int n_in,
                              void* d_out, int out_size)
{
    const float* x_init  = (const float*)d_in[0];
    const float* centers = (const float*)d_in[1];
    const float* stds    = (const float*)d_in[2];
    const float* weights = (const float*)d_in[3];
    const float* noise   = (const float*)d_in[4];
    float* out = (float*)d_out;

    sbm_kernel<<<NBLK, TPB>>>(x_init, centers, stds, weights, noise, out);
}